// round 13
// baseline (speedup 1.0000x reference)
#include <cuda_runtime.h>

// ---------------- problem constants (fixed by the reference) ----------------
#define NN   100000
#define MAXE 1600000

// ---------------- scratch (static __device__ globals: allowed) --------------
__device__ __align__(16) int   g_is32;            // 1 if edge_index is int32
__device__ __align__(16) int   g_off[NN + 1];     // degree -> exclusive offsets
__device__ __align__(16) int   g_cursor[NN];      // scatter cursors
__device__ __align__(16) int   g_bsums[128];      // scan block sums (raw totals)
__device__ __align__(16) int   g_srcsorted[MAXE]; // src ids sorted by dst
__device__ __align__(16) float g_invdeg[NN];      // 1/max(deg,1)
__device__ __align__(16) float g_p[NN * 64];      // p = h1 @ W2_l^T
__device__ __align__(16) float g_q[NN * 64];      // q = h1 @ W2_r^T

// ---------------- init: zero histogram + dtype detection ----------------------
// int64 little-endian node ids < 2^31 => every odd 32-bit word of the first
// 256 lanes is zero. int32 data => those words are (random) node ids.
#define ZB ((NN + 256) / 256)   // zero blocks; block ZB does detection
__global__ void k_init(const unsigned int* __restrict__ w) {
    if (blockIdx.x < ZB) {
        int i = blockIdx.x * 256 + threadIdx.x;
        if (i <= NN) g_off[i] = 0;
    } else {
        unsigned v = w[2 * threadIdx.x + 1];
        int any = __syncthreads_or(v != 0u);
        if (threadIdx.x == 0) g_is32 = any;
    }
}

// ---------------- degree histogram (reads dst half of edge_index directly) ----
__global__ void k_hist(const void* __restrict__ ei, int E) {
    int e = blockIdx.x * blockDim.x + threadIdx.x;
    if (e >= E) return;
    int d;
    if (g_is32) d = ((const int*)ei)[E + e];
    else        d = (int)((const long long*)ei)[E + e];
    d &= 0x7fffffff; if (d >= NN) d %= NN;
    atomicAdd(&g_off[d], 1);
}

// ---------------- 2-pass exclusive scan over degrees ---------------------------
// scanA: per-1024-chunk exclusive scan, chunk totals -> g_bsums (raw).
// scanC: each block locally prefix-sums the 98 chunk totals (cheap, parallel)
//        and produces final offsets + cursors. No serialized middle kernel.
__global__ void k_scanA(int n) {
    __shared__ int ws[32];
    int i = blockIdx.x * 1024 + threadIdx.x;
    int v = (i < n) ? g_off[i] : 0;
    if (i < n) g_invdeg[i] = 1.0f / (float)(v > 0 ? v : 1);
    int lane = threadIdx.x & 31, warp = threadIdx.x >> 5;
    int x = v;
#pragma unroll
    for (int o = 1; o < 32; o <<= 1) {
        int y = __shfl_up_sync(0xffffffffu, x, o);
        if (lane >= o) x += y;
    }
    if (lane == 31) ws[warp] = x;
    __syncthreads();
    if (threadIdx.x == 0) {
        int r = 0;
        for (int w = 0; w < 32; w++) { int t = ws[w]; ws[w] = r; r += t; }
        g_bsums[blockIdx.x] = r;     // raw chunk total
    }
    __syncthreads();
    if (i < n) g_off[i] = x - v + ws[warp];
}

__global__ void k_scanC(int n, int E, int nb) {
    __shared__ int pre[128];
    int tid = threadIdx.x;
    if (tid < nb) pre[tid] = g_bsums[tid];
    __syncthreads();
    if (tid == 0) {
        int r = 0;
        for (int w = 0; w < nb; w++) { int t = pre[w]; pre[w] = r; r += t; }
    }
    __syncthreads();
    int i = blockIdx.x * 256 + tid;
    if (i < n) {
        int o = g_off[i] + pre[i >> 10];
        g_off[i]    = o;
        g_cursor[i] = o;
    }
    if (i == 0) g_off[n] = E;
}

// ---------------- scatter src ids into CSR order (decodes ei directly) ---------
__global__ void k_scatter(const void* __restrict__ ei, int E) {
    int e = blockIdx.x * blockDim.x + threadIdx.x;
    if (e >= E) return;
    int s, d;
    if (g_is32) {
        const int* p = (const int*)ei;
        s = p[e]; d = p[E + e];
    } else {
        const long long* p = (const long long*)ei;
        s = (int)p[e]; d = (int)p[E + e];
    }
    s &= 0x7fffffff; if (s >= NN) s %= NN;
    d &= 0x7fffffff; if (d >= NN) d %= NN;
    int pos = atomicAdd(&g_cursor[d], 1);
    g_srcsorted[pos] = s;
}

// ---------------- layer-2 aggregation with fused epilogue -----------------------
// 16 threads per node, one float4 lane each; 4-edge unroll for MLP.
// feats = g_p (device global, referenced IN DEVICE CODE — never pass a
// __device__ array through a host-side kernel arg: on GB300 the host shadow
// address is ATS-dereferenceable and silently reads garbage).
// out = relu(mean(p) + b2 + q).
__global__ void k_agg2(const float* __restrict__ b2, float* __restrict__ out) {
    int node = blockIdx.x * 16 + (threadIdx.x >> 4);
    int l    = threadIdx.x & 15;
    if (node >= NN) return;
    const float4* f4 = (const float4*)g_p;
    int s = g_off[node], e = g_off[node + 1];
    float4 acc = make_float4(0.f, 0.f, 0.f, 0.f);
    int j = s;
    for (; j + 4 <= e; j += 4) {
        int i0 = __ldg(&g_srcsorted[j]);
        int i1 = __ldg(&g_srcsorted[j + 1]);
        int i2 = __ldg(&g_srcsorted[j + 2]);
        int i3 = __ldg(&g_srcsorted[j + 3]);
        float4 a0 = __ldg(&f4[i0 * 16 + l]);
        float4 a1 = __ldg(&f4[i1 * 16 + l]);
        float4 a2 = __ldg(&f4[i2 * 16 + l]);
        float4 a3 = __ldg(&f4[i3 * 16 + l]);
        acc.x += (a0.x + a1.x) + (a2.x + a3.x);
        acc.y += (a0.y + a1.y) + (a2.y + a3.y);
        acc.z += (a0.z + a1.z) + (a2.z + a3.z);
        acc.w += (a0.w + a1.w) + (a2.w + a3.w);
    }
    for (; j < e; j++) {
        int i0 = __ldg(&g_srcsorted[j]);
        float4 a = __ldg(&f4[i0 * 16 + l]);
        acc.x += a.x; acc.y += a.y; acc.z += a.z; acc.w += a.w;
    }
    float inv = g_invdeg[node];
    float4 bb = __ldg(&((const float4*)b2)[l]);
    float4 qq = ((const float4*)g_q)[node * 16 + l];
    float4 r;
    r.x = fmaxf(fmaf(acc.x, inv, bb.x + qq.x), 0.f);
    r.y = fmaxf(fmaf(acc.y, inv, bb.y + qq.y), 0.f);
    r.z = fmaxf(fmaf(acc.z, inv, bb.z + qq.z), 0.f);
    r.w = fmaxf(fmaf(acc.w, inv, bb.w + qq.w), 0.f);
    ((float4*)out)[node * 16 + l] = r;
}

// ---------------- fused agg1 + double GEMM (in-place smem reuse) -------------------
// Per 64-node tile (2 blocks/SM, 16 warps — occupancy is load-bearing):
//   phase 0: gather-mean x over neighbors DIRECTLY into smem Vs[:,0:64];
//            Vs[:,64:128] <- x; Ws <- W1          (g_agg round-trip eliminated)
//   phase 1: acc = V @ W1^T                        (H sub-tile lives in registers)
//   Vs <- relu(acc + b1) in place; Ws <- W2
//   phase 2: p|q = H @ W2^T -> g_p / g_q
#define GPITCH 130   // floats per smem row (u64 pitch 65 => conflict-free)
#define GSMEM  ((128 * GPITCH + 64 * GPITCH) * 4)

__global__ void __launch_bounds__(256, 2) k_gemm_fused(
    const float* __restrict__ xin,
    const float* __restrict__ W1l,   // [128,64]
    const float* __restrict__ W1r,   // [128,64]
    const float* __restrict__ b1,    // [128]
    const float* __restrict__ W2l,   // [64,128]
    const float* __restrict__ W2r)   // [64,128]
{
    extern __shared__ float sm[];
    float* Ws = sm;                    // [128][GPITCH] weights (W1 then W2)
    float* Vs = sm + 128 * GPITCH;     // [64][GPITCH]  values (V then H)
    int tid = threadIdx.x;
    int node0 = blockIdx.x * 64;

    // ---- W1 fill ----
    for (int idx = tid; idx < 128 * 128; idx += 256) {
        int c = idx >> 7, k = idx & 127;
        Ws[c * GPITCH + k] = (k < 64) ? W1l[c * 64 + k] : W1r[c * 64 + (k - 64)];
    }

    // ---- phase 0: gather-mean into Vs[:,0:64] (16 lanes/node, 4 node groups) ----
    {
        const float4* f4 = (const float4*)xin;
        int l = tid & 15;                 // float4 lane -> cols 4l..4l+3
#pragma unroll
        for (int g = 0; g < 4; g++) {
            int m = (tid >> 4) + g * 16;  // 0..63
            int node = node0 + m;
            float4 acc = make_float4(0.f, 0.f, 0.f, 0.f);
            if (node < NN) {
                int s = g_off[node], e = g_off[node + 1];
                int j = s;
                for (; j + 4 <= e; j += 4) {
                    int i0 = __ldg(&g_srcsorted[j]);
                    int i1 = __ldg(&g_srcsorted[j + 1]);
                    int i2 = __ldg(&g_srcsorted[j + 2]);
                    int i3 = __ldg(&g_srcsorted[j + 3]);
                    float4 a0 = __ldg(&f4[i0 * 16 + l]);
                    float4 a1 = __ldg(&f4[i1 * 16 + l]);
                    float4 a2 = __ldg(&f4[i2 * 16 + l]);
                    float4 a3 = __ldg(&f4[i3 * 16 + l]);
                    acc.x += (a0.x + a1.x) + (a2.x + a3.x);
                    acc.y += (a0.y + a1.y) + (a2.y + a3.y);
                    acc.z += (a0.z + a1.z) + (a2.z + a3.z);
                    acc.w += (a0.w + a1.w) + (a2.w + a3.w);
                }
                for (; j < e; j++) {
                    int i0 = __ldg(&g_srcsorted[j]);
                    float4 a = __ldg(&f4[i0 * 16 + l]);
                    acc.x += a.x; acc.y += a.y; acc.z += a.z; acc.w += a.w;
                }
                float inv = g_invdeg[node];
                acc.x *= inv; acc.y *= inv; acc.z *= inv; acc.w *= inv;
            }
            // scalar stores: float4 STS would be 8B-misaligned at odd rows (pitch 520B)
            float* vrow = Vs + m * GPITCH + 4 * l;
            vrow[0] = acc.x; vrow[1] = acc.y; vrow[2] = acc.z; vrow[3] = acc.w;
        }
        // x half: Vs[:,64:128]
        for (int idx = tid; idx < 64 * 64; idx += 256) {
            int m = idx >> 6, k = idx & 63;
            int node = node0 + m;
            Vs[m * GPITCH + 64 + k] = (node < NN) ? xin[node * 64 + k] : 0.f;
        }
    }
    __syncthreads();

    const unsigned long long* W2p = (const unsigned long long*)Ws;
    const unsigned long long* V2p = (const unsigned long long*)Vs;
    int cidx = tid & 15;   // cols cidx + 16j, j=0..7
    int midx = tid >> 4;   // rows midx*4 .. +3

    unsigned long long acc[4][8];
#pragma unroll
    for (int i = 0; i < 4; i++)
#pragma unroll
        for (int j = 0; j < 8; j++) acc[i][j] = 0ull;

    // ---- phase 1: acc = V @ W1^T ----
#pragma unroll 2
    for (int k2 = 0; k2 < 64; k2++) {
        unsigned long long w[8], v[4];
#pragma unroll
        for (int j = 0; j < 8; j++) w[j] = W2p[(cidx + 16 * j) * 65 + k2];
#pragma unroll
        for (int i = 0; i < 4; i++) v[i] = V2p[(midx * 4 + i) * 65 + k2];
#pragma unroll
        for (int i = 0; i < 4; i++)
#pragma unroll
            for (int j = 0; j < 8; j++)
                asm("fma.rn.f32x2 %0, %1, %2, %0;"
                    : "+l"(acc[i][j]) : "l"(v[i]), "l"(w[j]));
    }
    __syncthreads();   // all phase-1 smem reads done; safe to overwrite

    // ---- H = relu(acc + b1) IN PLACE over Vs; reload Ws <- W2 ----
#pragma unroll
    for (int i = 0; i < 4; i++) {
        int m = midx * 4 + i;
#pragma unroll
        for (int j = 0; j < 8; j++) {
            int c = cidx + 16 * j;
            float2 pr = *(float2*)&acc[i][j];
            Vs[m * GPITCH + c] = fmaxf(pr.x + pr.y + b1[c], 0.f);
            acc[i][j] = 0ull;   // reuse accumulators for phase 2
        }
    }
    for (int idx = tid; idx < 128 * 128; idx += 256) {
        int c = idx >> 7, k = idx & 127;
        Ws[c * GPITCH + k] = (c < 64) ? W2l[c * 128 + k] : W2r[(c - 64) * 128 + k];
    }
    __syncthreads();

    // ---- phase 2: p|q = H @ W2^T ----
#pragma unroll 2
    for (int k2 = 0; k2 < 64; k2++) {
        unsigned long long w[8], v[4];
#pragma unroll
        for (int j = 0; j < 8; j++) w[j] = W2p[(cidx + 16 * j) * 65 + k2];
#pragma unroll
        for (int i = 0; i < 4; i++) v[i] = V2p[(midx * 4 + i) * 65 + k2];
#pragma unroll
        for (int i = 0; i < 4; i++)
#pragma unroll
            for (int j = 0; j < 8; j++)
                asm("fma.rn.f32x2 %0, %1, %2, %0;"
                    : "+l"(acc[i][j]) : "l"(v[i]), "l"(w[j]));
    }

#pragma unroll
    for (int i = 0; i < 4; i++) {
        int node = node0 + midx * 4 + i;
        if (node < NN) {
#pragma unroll
            for (int j = 0; j < 8; j++) {
                int c = cidx + 16 * j;
                float2 pr = *(float2*)&acc[i][j];
                float r = pr.x + pr.y;
                if (c < 64) g_p[node * 64 + c] = r;
                else        g_q[node * 64 + (c - 64)] = r;
            }
        }
    }
}

// ---------------- launch ----------------------------------------------------------
extern "C" void kernel_launch(void* const* d_in, const int* in_sizes, int n_in,
                              void* d_out, int out_size) {
    const float* x   = (const float*)d_in[0];
    const void*  ei  = d_in[1];
    const float* W1l = (const float*)d_in[2];
    const float* b1  = (const float*)d_in[3];
    const float* W1r = (const float*)d_in[4];
    const float* W2l = (const float*)d_in[5];
    const float* b2  = (const float*)d_in[6];
    const float* W2r = (const float*)d_in[7];
    float* out = (float*)d_out;

    int E = in_sizes[1] / 2;   // element count of (2, E) for either dtype
    if (E > MAXE) E = MAXE;

    cudaFuncSetAttribute((const void*)k_gemm_fused,
                         cudaFuncAttributeMaxDynamicSharedMemorySize, GSMEM);

    const int NB_SCAN = (NN + 1023) / 1024;            // 98
    const int GB      = (NN + 63) / 64;                // gemm blocks: 1563
    const int AB      = (NN + 15) / 16;                // agg blocks: 6250

    // --- init (zero hist + dtype detect) + build CSR (scanB folded into scanC) ---
    k_init<<<ZB + 1, 256>>>((const unsigned int*)ei);
    k_hist<<<(E + 255) / 256, 256>>>(ei, E);
    k_scanA<<<NB_SCAN, 1024>>>(NN);
    k_scanC<<<(NN + 255) / 256, 256>>>(NN, E, NB_SCAN);
    k_scatter<<<(E + 255) / 256, 256>>>(ei, E);

    // --- layer 1 agg + BOTH layers' linear parts in ONE kernel ---
    k_gemm_fused<<<GB, 256, GSMEM>>>(x, W1l, W1r, b1, W2l, W2r);

    // --- layer 2: aggregate p with fused epilogue ---
    k_agg2<<<AB, 256>>>(b2, out);
}

// round 14
// speedup vs baseline: 1.0072x; 1.0072x over previous
#include <cuda_runtime.h>

// ---------------- problem constants (fixed by the reference) ----------------
#define NN   100000
#define MAXE 1600000

// ---------------- scratch (static __device__ globals: allowed) --------------
__device__ __align__(16) int   g_is32;            // 1 if edge_index is int32
__device__ __align__(16) int   g_off[NN + 1];     // degree -> exclusive offsets
__device__ __align__(16) int   g_cursor[NN];      // scatter cursors
__device__ __align__(16) int   g_bsums[128];      // scan block sums (raw totals)
__device__ __align__(16) int   g_srcsorted[MAXE]; // src ids sorted by dst
__device__ __align__(16) float g_invdeg[NN];      // 1/max(deg,1)
__device__ __align__(16) float g_p[NN * 64];      // p = h1 @ W2_l^T
__device__ __align__(16) float g_q[NN * 64];      // q = h1 @ W2_r^T

// ---------------- init: zero histogram + dtype detection ----------------------
// int64 little-endian node ids < 2^31 => every odd 32-bit word of the first
// 256 lanes is zero. int32 data => those words are (random) node ids.
#define ZB ((NN + 256) / 256)   // zero blocks; block ZB does detection
__global__ void k_init(const unsigned int* __restrict__ w) {
    if (blockIdx.x < ZB) {
        int i = blockIdx.x * 256 + threadIdx.x;
        if (i <= NN) g_off[i] = 0;
    } else {
        unsigned v = w[2 * threadIdx.x + 1];
        int any = __syncthreads_or(v != 0u);
        if (threadIdx.x == 0) g_is32 = any;
    }
}

// ---------------- degree histogram (reads dst half of edge_index directly) ----
__global__ void k_hist(const void* __restrict__ ei, int E) {
    int e = blockIdx.x * blockDim.x + threadIdx.x;
    if (e >= E) return;
    int d;
    if (g_is32) d = ((const int*)ei)[E + e];
    else        d = (int)((const long long*)ei)[E + e];
    d &= 0x7fffffff; if (d >= NN) d %= NN;
    atomicAdd(&g_off[d], 1);
}

// ---------------- 2-pass exclusive scan over degrees ---------------------------
// scanA: per-1024-chunk exclusive scan, chunk totals -> g_bsums (raw).
// scanC: each block locally prefix-sums the 98 chunk totals (cheap, parallel)
//        and produces final offsets + cursors. No serialized middle kernel.
__global__ void k_scanA(int n) {
    __shared__ int ws[32];
    int i = blockIdx.x * 1024 + threadIdx.x;
    int v = (i < n) ? g_off[i] : 0;
    if (i < n) g_invdeg[i] = 1.0f / (float)(v > 0 ? v : 1);
    int lane = threadIdx.x & 31, warp = threadIdx.x >> 5;
    int x = v;
#pragma unroll
    for (int o = 1; o < 32; o <<= 1) {
        int y = __shfl_up_sync(0xffffffffu, x, o);
        if (lane >= o) x += y;
    }
    if (lane == 31) ws[warp] = x;
    __syncthreads();
    if (threadIdx.x == 0) {
        int r = 0;
        for (int w = 0; w < 32; w++) { int t = ws[w]; ws[w] = r; r += t; }
        g_bsums[blockIdx.x] = r;     // raw chunk total
    }
    __syncthreads();
    if (i < n) g_off[i] = x - v + ws[warp];
}

__global__ void k_scanC(int n, int E, int nb) {
    __shared__ int pre[128];
    int tid = threadIdx.x;
    if (tid < nb) pre[tid] = g_bsums[tid];
    __syncthreads();
    if (tid == 0) {
        int r = 0;
        for (int w = 0; w < nb; w++) { int t = pre[w]; pre[w] = r; r += t; }
    }
    __syncthreads();
    int i = blockIdx.x * 256 + tid;
    if (i < n) {
        int o = g_off[i] + pre[i >> 10];
        g_off[i]    = o;
        g_cursor[i] = o;
    }
    if (i == 0) g_off[n] = E;
}

// ---------------- scatter src ids into CSR order (decodes ei directly) ---------
__global__ void k_scatter(const void* __restrict__ ei, int E) {
    int e = blockIdx.x * blockDim.x + threadIdx.x;
    if (e >= E) return;
    int s, d;
    if (g_is32) {
        const int* p = (const int*)ei;
        s = p[e]; d = p[E + e];
    } else {
        const long long* p = (const long long*)ei;
        s = (int)p[e]; d = (int)p[E + e];
    }
    s &= 0x7fffffff; if (s >= NN) s %= NN;
    d &= 0x7fffffff; if (d >= NN) d %= NN;
    int pos = atomicAdd(&g_cursor[d], 1);
    g_srcsorted[pos] = s;
}

// ---------------- layer-2 aggregation with fused epilogue -----------------------
// 16 threads per node, one float4 lane each; 4-edge unroll for MLP.
// feats = g_p (device global, referenced IN DEVICE CODE — never pass a
// __device__ array through a host-side kernel arg: on GB300 the host shadow
// address is ATS-dereferenceable and silently reads garbage).
// out = relu(mean(p) + b2 + q).
__global__ void k_agg2(const float* __restrict__ b2, float* __restrict__ out) {
    int node = blockIdx.x * 16 + (threadIdx.x >> 4);
    int l    = threadIdx.x & 15;
    if (node >= NN) return;
    const float4* f4 = (const float4*)g_p;
    int s = g_off[node], e = g_off[node + 1];
    float4 acc = make_float4(0.f, 0.f, 0.f, 0.f);
    int j = s;
    for (; j + 4 <= e; j += 4) {
        int i0 = __ldg(&g_srcsorted[j]);
        int i1 = __ldg(&g_srcsorted[j + 1]);
        int i2 = __ldg(&g_srcsorted[j + 2]);
        int i3 = __ldg(&g_srcsorted[j + 3]);
        float4 a0 = __ldg(&f4[i0 * 16 + l]);
        float4 a1 = __ldg(&f4[i1 * 16 + l]);
        float4 a2 = __ldg(&f4[i2 * 16 + l]);
        float4 a3 = __ldg(&f4[i3 * 16 + l]);
        acc.x += (a0.x + a1.x) + (a2.x + a3.x);
        acc.y += (a0.y + a1.y) + (a2.y + a3.y);
        acc.z += (a0.z + a1.z) + (a2.z + a3.z);
        acc.w += (a0.w + a1.w) + (a2.w + a3.w);
    }
    for (; j < e; j++) {
        int i0 = __ldg(&g_srcsorted[j]);
        float4 a = __ldg(&f4[i0 * 16 + l]);
        acc.x += a.x; acc.y += a.y; acc.z += a.z; acc.w += a.w;
    }
    float inv = g_invdeg[node];
    float4 bb = __ldg(&((const float4*)b2)[l]);
    float4 qq = ((const float4*)g_q)[node * 16 + l];
    float4 r;
    r.x = fmaxf(fmaf(acc.x, inv, bb.x + qq.x), 0.f);
    r.y = fmaxf(fmaf(acc.y, inv, bb.y + qq.y), 0.f);
    r.z = fmaxf(fmaf(acc.z, inv, bb.z + qq.z), 0.f);
    r.w = fmaxf(fmaf(acc.w, inv, bb.w + qq.w), 0.f);
    ((float4*)out)[node * 16 + l] = r;
}

// ---------------- fused agg1 + double GEMM (in-place smem reuse) -------------------
// Per 64-node tile (2 blocks/SM, 16 warps — occupancy is load-bearing):
//   phase 0: gather-mean x over neighbors DIRECTLY into smem Vs[:,0:64];
//            Vs[:,64:128] <- x; Ws <- W1          (g_agg round-trip eliminated)
//   phase 1: acc = V @ W1^T                        (H sub-tile lives in registers)
//   Vs <- relu(acc + b1) in place; Ws <- W2
//   phase 2: p|q = H @ W2^T -> g_p / g_q
#define GPITCH 130   // floats per smem row (u64 pitch 65 => conflict-free)
#define GSMEM  ((128 * GPITCH + 64 * GPITCH) * 4)

__global__ void __launch_bounds__(256, 2) k_gemm_fused(
    const float* __restrict__ xin,
    const float* __restrict__ W1l,   // [128,64]
    const float* __restrict__ W1r,   // [128,64]
    const float* __restrict__ b1,    // [128]
    const float* __restrict__ W2l,   // [64,128]
    const float* __restrict__ W2r)   // [64,128]
{
    extern __shared__ float sm[];
    float* Ws = sm;                    // [128][GPITCH] weights (W1 then W2)
    float* Vs = sm + 128 * GPITCH;     // [64][GPITCH]  values (V then H)
    int tid = threadIdx.x;
    int node0 = blockIdx.x * 64;

    // ---- W1 fill ----
    for (int idx = tid; idx < 128 * 128; idx += 256) {
        int c = idx >> 7, k = idx & 127;
        Ws[c * GPITCH + k] = (k < 64) ? W1l[c * 64 + k] : W1r[c * 64 + (k - 64)];
    }

    // ---- phase 0: gather-mean into Vs[:,0:64] (16 lanes/node, 4 node groups) ----
    {
        const float4* f4 = (const float4*)xin;
        int l = tid & 15;                 // float4 lane -> cols 4l..4l+3
#pragma unroll
        for (int g = 0; g < 4; g++) {
            int m = (tid >> 4) + g * 16;  // 0..63
            int node = node0 + m;
            float4 acc = make_float4(0.f, 0.f, 0.f, 0.f);
            if (node < NN) {
                int s = g_off[node], e = g_off[node + 1];
                int j = s;
                for (; j + 4 <= e; j += 4) {
                    int i0 = __ldg(&g_srcsorted[j]);
                    int i1 = __ldg(&g_srcsorted[j + 1]);
                    int i2 = __ldg(&g_srcsorted[j + 2]);
                    int i3 = __ldg(&g_srcsorted[j + 3]);
                    float4 a0 = __ldg(&f4[i0 * 16 + l]);
                    float4 a1 = __ldg(&f4[i1 * 16 + l]);
                    float4 a2 = __ldg(&f4[i2 * 16 + l]);
                    float4 a3 = __ldg(&f4[i3 * 16 + l]);
                    acc.x += (a0.x + a1.x) + (a2.x + a3.x);
                    acc.y += (a0.y + a1.y) + (a2.y + a3.y);
                    acc.z += (a0.z + a1.z) + (a2.z + a3.z);
                    acc.w += (a0.w + a1.w) + (a2.w + a3.w);
                }
                for (; j < e; j++) {
                    int i0 = __ldg(&g_srcsorted[j]);
                    float4 a = __ldg(&f4[i0 * 16 + l]);
                    acc.x += a.x; acc.y += a.y; acc.z += a.z; acc.w += a.w;
                }
                float inv = g_invdeg[node];
                acc.x *= inv; acc.y *= inv; acc.z *= inv; acc.w *= inv;
            }
            // scalar stores: float4 STS would be 8B-misaligned at odd rows (pitch 520B)
            float* vrow = Vs + m * GPITCH + 4 * l;
            vrow[0] = acc.x; vrow[1] = acc.y; vrow[2] = acc.z; vrow[3] = acc.w;
        }
        // x half: Vs[:,64:128]
        for (int idx = tid; idx < 64 * 64; idx += 256) {
            int m = idx >> 6, k = idx & 63;
            int node = node0 + m;
            Vs[m * GPITCH + 64 + k] = (node < NN) ? xin[node * 64 + k] : 0.f;
        }
    }
    __syncthreads();

    const unsigned long long* W2p = (const unsigned long long*)Ws;
    const unsigned long long* V2p = (const unsigned long long*)Vs;
    int cidx = tid & 15;   // cols cidx + 16j, j=0..7
    int midx = tid >> 4;   // rows midx*4 .. +3

    unsigned long long acc[4][8];
#pragma unroll
    for (int i = 0; i < 4; i++)
#pragma unroll
        for (int j = 0; j < 8; j++) acc[i][j] = 0ull;

    // ---- phase 1: acc = V @ W1^T ----
#pragma unroll 2
    for (int k2 = 0; k2 < 64; k2++) {
        unsigned long long w[8], v[4];
#pragma unroll
        for (int j = 0; j < 8; j++) w[j] = W2p[(cidx + 16 * j) * 65 + k2];
#pragma unroll
        for (int i = 0; i < 4; i++) v[i] = V2p[(midx * 4 + i) * 65 + k2];
#pragma unroll
        for (int i = 0; i < 4; i++)
#pragma unroll
            for (int j = 0; j < 8; j++)
                asm("fma.rn.f32x2 %0, %1, %2, %0;"
                    : "+l"(acc[i][j]) : "l"(v[i]), "l"(w[j]));
    }
    __syncthreads();   // all phase-1 smem reads done; safe to overwrite

    // ---- H = relu(acc + b1) IN PLACE over Vs; reload Ws <- W2 ----
#pragma unroll
    for (int i = 0; i < 4; i++) {
        int m = midx * 4 + i;
#pragma unroll
        for (int j = 0; j < 8; j++) {
            int c = cidx + 16 * j;
            float2 pr = *(float2*)&acc[i][j];
            Vs[m * GPITCH + c] = fmaxf(pr.x + pr.y + b1[c], 0.f);
            acc[i][j] = 0ull;   // reuse accumulators for phase 2
        }
    }
    for (int idx = tid; idx < 128 * 128; idx += 256) {
        int c = idx >> 7, k = idx & 127;
        Ws[c * GPITCH + k] = (c < 64) ? W2l[c * 128 + k] : W2r[(c - 64) * 128 + k];
    }
    __syncthreads();

    // ---- phase 2: p|q = H @ W2^T ----
#pragma unroll 2
    for (int k2 = 0; k2 < 64; k2++) {
        unsigned long long w[8], v[4];
#pragma unroll
        for (int j = 0; j < 8; j++) w[j] = W2p[(cidx + 16 * j) * 65 + k2];
#pragma unroll
        for (int i = 0; i < 4; i++) v[i] = V2p[(midx * 4 + i) * 65 + k2];
#pragma unroll
        for (int i = 0; i < 4; i++)
#pragma unroll
            for (int j = 0; j < 8; j++)
                asm("fma.rn.f32x2 %0, %1, %2, %0;"
                    : "+l"(acc[i][j]) : "l"(v[i]), "l"(w[j]));
    }

#pragma unroll
    for (int i = 0; i < 4; i++) {
        int node = node0 + midx * 4 + i;
        if (node < NN) {
#pragma unroll
            for (int j = 0; j < 8; j++) {
                int c = cidx + 16 * j;
                float2 pr = *(float2*)&acc[i][j];
                float r = pr.x + pr.y;
                if (c < 64) g_p[node * 64 + c] = r;
                else        g_q[node * 64 + (c - 64)] = r;
            }
        }
    }
}

// ---------------- launch ----------------------------------------------------------
extern "C" void kernel_launch(void* const* d_in, const int* in_sizes, int n_in,
                              void* d_out, int out_size) {
    const float* x   = (const float*)d_in[0];
    const void*  ei  = d_in[1];
    const float* W1l = (const float*)d_in[2];
    const float* b1  = (const float*)d_in[3];
    const float* W1r = (const float*)d_in[4];
    const float* W2l = (const float*)d_in[5];
    const float* b2  = (const float*)d_in[6];
    const float* W2r = (const float*)d_in[7];
    float* out = (float*)d_out;

    int E = in_sizes[1] / 2;   // element count of (2, E) for either dtype
    if (E > MAXE) E = MAXE;

    cudaFuncSetAttribute((const void*)k_gemm_fused,
                         cudaFuncAttributeMaxDynamicSharedMemorySize, GSMEM);

    const int NB_SCAN = (NN + 1023) / 1024;            // 98
    const int GB      = (NN + 63) / 64;                // gemm blocks: 1563
    const int AB      = (NN + 15) / 16;                // agg blocks: 6250

    // --- init (zero hist + dtype detect) + build CSR (scanB folded into scanC) ---
    k_init<<<ZB + 1, 256>>>((const unsigned int*)ei);
    k_hist<<<(E + 255) / 256, 256>>>(ei, E);
    k_scanA<<<NB_SCAN, 1024>>>(NN);
    k_scanC<<<(NN + 255) / 256, 256>>>(NN, E, NB_SCAN);
    k_scatter<<<(E + 255) / 256, 256>>>(ei, E);

    // --- layer 1 agg + BOTH layers' linear parts in ONE kernel ---
    k_gemm_fused<<<GB, 256, GSMEM>>>(x, W1l, W1r, b1, W2l, W2r);

    // --- layer 2: aggregate p with fused epilogue ---
    k_agg2<<<AB, 256>>>(b2, out);
}

// round 15
// speedup vs baseline: 1.0083x; 1.0010x over previous
#include <cuda_runtime.h>

// ---------------- problem constants (fixed by the reference) ----------------
#define NN   100000
#define MAXE 1600000

// ---------------- scratch (static __device__ globals: allowed) --------------
__device__ __align__(16) int   g_is32;            // 1 if edge_index is int32
__device__ __align__(16) int   g_off[NN + 1];     // degree -> exclusive offsets
__device__ __align__(16) int   g_cursor[NN];      // scatter cursors
__device__ __align__(16) int   g_bsums[128];      // scan block sums (raw totals)
__device__ __align__(16) int   g_srcsorted[MAXE]; // src ids sorted by dst
__device__ __align__(16) float g_invdeg[NN];      // 1/max(deg,1)
__device__ __align__(16) float g_p[NN * 64];      // p = h1 @ W2_l^T
__device__ __align__(16) float g_q[NN * 64];      // q = h1 @ W2_r^T

// ---------------- init: zero histogram + dtype detection ----------------------
// int64 little-endian node ids < 2^31 => every odd 32-bit word of the first
// 256 lanes is zero. int32 data => those words are (random) node ids.
#define ZB ((NN + 256) / 256)   // zero blocks; block ZB does detection
__global__ void k_init(const unsigned int* __restrict__ w) {
    if (blockIdx.x < ZB) {
        int i = blockIdx.x * 256 + threadIdx.x;
        if (i <= NN) g_off[i] = 0;
    } else {
        unsigned v = w[2 * threadIdx.x + 1];
        int any = __syncthreads_or(v != 0u);
        if (threadIdx.x == 0) g_is32 = any;
    }
}

// ---------------- degree histogram (reads dst half of edge_index directly) ----
__global__ void k_hist(const void* __restrict__ ei, int E) {
    int e = blockIdx.x * blockDim.x + threadIdx.x;
    if (e >= E) return;
    int d;
    if (g_is32) d = ((const int*)ei)[E + e];
    else        d = (int)((const long long*)ei)[E + e];
    d &= 0x7fffffff; if (d >= NN) d %= NN;
    atomicAdd(&g_off[d], 1);
}

// ---------------- 2-pass exclusive scan over degrees ---------------------------
// scanA: per-1024-chunk exclusive scan, chunk totals -> g_bsums (raw).
// scanC: each block locally prefix-sums the 98 chunk totals (cheap, parallel)
//        and produces final offsets + cursors. No serialized middle kernel.
__global__ void k_scanA(int n) {
    __shared__ int ws[32];
    int i = blockIdx.x * 1024 + threadIdx.x;
    int v = (i < n) ? g_off[i] : 0;
    if (i < n) g_invdeg[i] = 1.0f / (float)(v > 0 ? v : 1);
    int lane = threadIdx.x & 31, warp = threadIdx.x >> 5;
    int x = v;
#pragma unroll
    for (int o = 1; o < 32; o <<= 1) {
        int y = __shfl_up_sync(0xffffffffu, x, o);
        if (lane >= o) x += y;
    }
    if (lane == 31) ws[warp] = x;
    __syncthreads();
    if (threadIdx.x == 0) {
        int r = 0;
        for (int w = 0; w < 32; w++) { int t = ws[w]; ws[w] = r; r += t; }
        g_bsums[blockIdx.x] = r;     // raw chunk total
    }
    __syncthreads();
    if (i < n) g_off[i] = x - v + ws[warp];
}

__global__ void k_scanC(int n, int E, int nb) {
    __shared__ int pre[128];
    int tid = threadIdx.x;
    if (tid < nb) pre[tid] = g_bsums[tid];
    __syncthreads();
    if (tid == 0) {
        int r = 0;
        for (int w = 0; w < nb; w++) { int t = pre[w]; pre[w] = r; r += t; }
    }
    __syncthreads();
    int i = blockIdx.x * 256 + tid;
    if (i < n) {
        int o = g_off[i] + pre[i >> 10];
        g_off[i]    = o;
        g_cursor[i] = o;
    }
    if (i == 0) g_off[n] = E;
}

// ---------------- scatter src ids into CSR order (decodes ei directly) ---------
__global__ void k_scatter(const void* __restrict__ ei, int E) {
    int e = blockIdx.x * blockDim.x + threadIdx.x;
    if (e >= E) return;
    int s, d;
    if (g_is32) {
        const int* p = (const int*)ei;
        s = p[e]; d = p[E + e];
    } else {
        const long long* p = (const long long*)ei;
        s = (int)p[e]; d = (int)p[E + e];
    }
    s &= 0x7fffffff; if (s >= NN) s %= NN;
    d &= 0x7fffffff; if (d >= NN) d %= NN;
    int pos = atomicAdd(&g_cursor[d], 1);
    g_srcsorted[pos] = s;
}

// ---------------- layer-2 aggregation with fused epilogue -----------------------
// 16 threads per node, one float4 lane each; 4-edge unroll for MLP.
// feats = g_p (device global, referenced IN DEVICE CODE — never pass a
// __device__ array through a host-side kernel arg: on GB300 the host shadow
// address is ATS-dereferenceable and silently reads garbage).
// out = relu(mean(p) + b2 + q).
__global__ void k_agg2(const float* __restrict__ b2, float* __restrict__ out) {
    int node = blockIdx.x * 16 + (threadIdx.x >> 4);
    int l    = threadIdx.x & 15;
    if (node >= NN) return;
    const float4* f4 = (const float4*)g_p;
    int s = g_off[node], e = g_off[node + 1];
    float4 acc = make_float4(0.f, 0.f, 0.f, 0.f);
    int j = s;
    for (; j + 4 <= e; j += 4) {
        int i0 = __ldg(&g_srcsorted[j]);
        int i1 = __ldg(&g_srcsorted[j + 1]);
        int i2 = __ldg(&g_srcsorted[j + 2]);
        int i3 = __ldg(&g_srcsorted[j + 3]);
        float4 a0 = __ldg(&f4[i0 * 16 + l]);
        float4 a1 = __ldg(&f4[i1 * 16 + l]);
        float4 a2 = __ldg(&f4[i2 * 16 + l]);
        float4 a3 = __ldg(&f4[i3 * 16 + l]);
        acc.x += (a0.x + a1.x) + (a2.x + a3.x);
        acc.y += (a0.y + a1.y) + (a2.y + a3.y);
        acc.z += (a0.z + a1.z) + (a2.z + a3.z);
        acc.w += (a0.w + a1.w) + (a2.w + a3.w);
    }
    for (; j < e; j++) {
        int i0 = __ldg(&g_srcsorted[j]);
        float4 a = __ldg(&f4[i0 * 16 + l]);
        acc.x += a.x; acc.y += a.y; acc.z += a.z; acc.w += a.w;
    }
    float inv = g_invdeg[node];
    float4 bb = __ldg(&((const float4*)b2)[l]);
    float4 qq = ((const float4*)g_q)[node * 16 + l];
    float4 r;
    r.x = fmaxf(fmaf(acc.x, inv, bb.x + qq.x), 0.f);
    r.y = fmaxf(fmaf(acc.y, inv, bb.y + qq.y), 0.f);
    r.z = fmaxf(fmaf(acc.z, inv, bb.z + qq.z), 0.f);
    r.w = fmaxf(fmaf(acc.w, inv, bb.w + qq.w), 0.f);
    ((float4*)out)[node * 16 + l] = r;
}

// ---------------- fused agg1 + double GEMM (in-place smem reuse) -------------------
// Per 64-node tile (2 blocks/SM, 16 warps — occupancy is load-bearing):
//   phase 0: gather-mean x over neighbors DIRECTLY into smem Vs[:,0:64];
//            Vs[:,64:128] <- x; Ws <- W1          (g_agg round-trip eliminated)
//   phase 1: acc = V @ W1^T                        (H sub-tile lives in registers)
//   Vs <- relu(acc + b1) in place; Ws <- W2
//   phase 2: p|q = H @ W2^T -> g_p / g_q
#define GPITCH 130   // floats per smem row (u64 pitch 65 => conflict-free)
#define GSMEM  ((128 * GPITCH + 64 * GPITCH) * 4)

__global__ void __launch_bounds__(256, 2) k_gemm_fused(
    const float* __restrict__ xin,
    const float* __restrict__ W1l,   // [128,64]
    const float* __restrict__ W1r,   // [128,64]
    const float* __restrict__ b1,    // [128]
    const float* __restrict__ W2l,   // [64,128]
    const float* __restrict__ W2r)   // [64,128]
{
    extern __shared__ float sm[];
    float* Ws = sm;                    // [128][GPITCH] weights (W1 then W2)
    float* Vs = sm + 128 * GPITCH;     // [64][GPITCH]  values (V then H)
    int tid = threadIdx.x;
    int node0 = blockIdx.x * 64;

    // ---- W1 fill ----
    for (int idx = tid; idx < 128 * 128; idx += 256) {
        int c = idx >> 7, k = idx & 127;
        Ws[c * GPITCH + k] = (k < 64) ? W1l[c * 64 + k] : W1r[c * 64 + (k - 64)];
    }

    // ---- phase 0: gather-mean into Vs[:,0:64] (16 lanes/node, 4 node groups) ----
    {
        const float4* f4 = (const float4*)xin;
        int l = tid & 15;                 // float4 lane -> cols 4l..4l+3
#pragma unroll
        for (int g = 0; g < 4; g++) {
            int m = (tid >> 4) + g * 16;  // 0..63
            int node = node0 + m;
            float4 acc = make_float4(0.f, 0.f, 0.f, 0.f);
            if (node < NN) {
                int s = g_off[node], e = g_off[node + 1];
                int j = s;
                for (; j + 4 <= e; j += 4) {
                    int i0 = __ldg(&g_srcsorted[j]);
                    int i1 = __ldg(&g_srcsorted[j + 1]);
                    int i2 = __ldg(&g_srcsorted[j + 2]);
                    int i3 = __ldg(&g_srcsorted[j + 3]);
                    float4 a0 = __ldg(&f4[i0 * 16 + l]);
                    float4 a1 = __ldg(&f4[i1 * 16 + l]);
                    float4 a2 = __ldg(&f4[i2 * 16 + l]);
                    float4 a3 = __ldg(&f4[i3 * 16 + l]);
                    acc.x += (a0.x + a1.x) + (a2.x + a3.x);
                    acc.y += (a0.y + a1.y) + (a2.y + a3.y);
                    acc.z += (a0.z + a1.z) + (a2.z + a3.z);
                    acc.w += (a0.w + a1.w) + (a2.w + a3.w);
                }
                for (; j < e; j++) {
                    int i0 = __ldg(&g_srcsorted[j]);
                    float4 a = __ldg(&f4[i0 * 16 + l]);
                    acc.x += a.x; acc.y += a.y; acc.z += a.z; acc.w += a.w;
                }
                float inv = g_invdeg[node];
                acc.x *= inv; acc.y *= inv; acc.z *= inv; acc.w *= inv;
            }
            // scalar stores: float4 STS would be 8B-misaligned at odd rows (pitch 520B)
            float* vrow = Vs + m * GPITCH + 4 * l;
            vrow[0] = acc.x; vrow[1] = acc.y; vrow[2] = acc.z; vrow[3] = acc.w;
        }
        // x half: Vs[:,64:128]
        for (int idx = tid; idx < 64 * 64; idx += 256) {
            int m = idx >> 6, k = idx & 63;
            int node = node0 + m;
            Vs[m * GPITCH + 64 + k] = (node < NN) ? xin[node * 64 + k] : 0.f;
        }
    }
    __syncthreads();

    const unsigned long long* W2p = (const unsigned long long*)Ws;
    const unsigned long long* V2p = (const unsigned long long*)Vs;
    int cidx = tid & 15;   // cols cidx + 16j, j=0..7
    int midx = tid >> 4;   // rows midx*4 .. +3

    unsigned long long acc[4][8];
#pragma unroll
    for (int i = 0; i < 4; i++)
#pragma unroll
        for (int j = 0; j < 8; j++) acc[i][j] = 0ull;

    // ---- phase 1: acc = V @ W1^T ----
#pragma unroll 2
    for (int k2 = 0; k2 < 64; k2++) {
        unsigned long long w[8], v[4];
#pragma unroll
        for (int j = 0; j < 8; j++) w[j] = W2p[(cidx + 16 * j) * 65 + k2];
#pragma unroll
        for (int i = 0; i < 4; i++) v[i] = V2p[(midx * 4 + i) * 65 + k2];
#pragma unroll
        for (int i = 0; i < 4; i++)
#pragma unroll
            for (int j = 0; j < 8; j++)
                asm("fma.rn.f32x2 %0, %1, %2, %0;"
                    : "+l"(acc[i][j]) : "l"(v[i]), "l"(w[j]));
    }
    __syncthreads();   // all phase-1 smem reads done; safe to overwrite

    // ---- H = relu(acc + b1) IN PLACE over Vs; reload Ws <- W2 ----
#pragma unroll
    for (int i = 0; i < 4; i++) {
        int m = midx * 4 + i;
#pragma unroll
        for (int j = 0; j < 8; j++) {
            int c = cidx + 16 * j;
            float2 pr = *(float2*)&acc[i][j];
            Vs[m * GPITCH + c] = fmaxf(pr.x + pr.y + b1[c], 0.f);
            acc[i][j] = 0ull;   // reuse accumulators for phase 2
        }
    }
    for (int idx = tid; idx < 128 * 128; idx += 256) {
        int c = idx >> 7, k = idx & 127;
        Ws[c * GPITCH + k] = (c < 64) ? W2l[c * 128 + k] : W2r[(c - 64) * 128 + k];
    }
    __syncthreads();

    // ---- phase 2: p|q = H @ W2^T ----
#pragma unroll 2
    for (int k2 = 0; k2 < 64; k2++) {
        unsigned long long w[8], v[4];
#pragma unroll
        for (int j = 0; j < 8; j++) w[j] = W2p[(cidx + 16 * j) * 65 + k2];
#pragma unroll
        for (int i = 0; i < 4; i++) v[i] = V2p[(midx * 4 + i) * 65 + k2];
#pragma unroll
        for (int i = 0; i < 4; i++)
#pragma unroll
            for (int j = 0; j < 8; j++)
                asm("fma.rn.f32x2 %0, %1, %2, %0;"
                    : "+l"(acc[i][j]) : "l"(v[i]), "l"(w[j]));
    }

#pragma unroll
    for (int i = 0; i < 4; i++) {
        int node = node0 + midx * 4 + i;
        if (node < NN) {
#pragma unroll
            for (int j = 0; j < 8; j++) {
                int c = cidx + 16 * j;
                float2 pr = *(float2*)&acc[i][j];
                float r = pr.x + pr.y;
                if (c < 64) g_p[node * 64 + c] = r;
                else        g_q[node * 64 + (c - 64)] = r;
            }
        }
    }
}

// ---------------- launch ----------------------------------------------------------
extern "C" void kernel_launch(void* const* d_in, const int* in_sizes, int n_in,
                              void* d_out, int out_size) {
    const float* x   = (const float*)d_in[0];
    const void*  ei  = d_in[1];
    const float* W1l = (const float*)d_in[2];
    const float* b1  = (const float*)d_in[3];
    const float* W1r = (const float*)d_in[4];
    const float* W2l = (const float*)d_in[5];
    const float* b2  = (const float*)d_in[6];
    const float* W2r = (const float*)d_in[7];
    float* out = (float*)d_out;

    int E = in_sizes[1] / 2;   // element count of (2, E) for either dtype
    if (E > MAXE) E = MAXE;

    cudaFuncSetAttribute((const void*)k_gemm_fused,
                         cudaFuncAttributeMaxDynamicSharedMemorySize, GSMEM);

    const int NB_SCAN = (NN + 1023) / 1024;            // 98
    const int GB      = (NN + 63) / 64;                // gemm blocks: 1563
    const int AB      = (NN + 15) / 16;                // agg blocks: 6250

    // --- init (zero hist + dtype detect) + build CSR (scanB folded into scanC) ---
    k_init<<<ZB + 1, 256>>>((const unsigned int*)ei);
    k_hist<<<(E + 255) / 256, 256>>>(ei, E);
    k_scanA<<<NB_SCAN, 1024>>>(NN);
    k_scanC<<<(NN + 255) / 256, 256>>>(NN, E, NB_SCAN);
    k_scatter<<<(E + 255) / 256, 256>>>(ei, E);

    // --- layer 1 agg + BOTH layers' linear parts in ONE kernel ---
    k_gemm_fused<<<GB, 256, GSMEM>>>(x, W1l, W1r, b1, W2l, W2r);

    // --- layer 2: aggregate p with fused epilogue ---
    k_agg2<<<AB, 256>>>(b2, out);
}